// round 14
// baseline (speedup 1.0000x reference)
#include <cuda_runtime.h>
#include <cuda_fp16.h>
#include <math.h>
#include <stdint.h>

// ---------------- scratch (fp16 pipeline) ----------------
__device__ __half g_xh  [4096 * 1024];   // x fp16
__device__ __half g_wqT [3072 * 1024];   // w_qkv^T fp16  [N][K]
__device__ __half g_wpT [1024 * 1024];   // w_proj^T fp16 [N][K]
__device__ __half g_qkvh[4096 * 3072];   // qkv fp16
__device__ __half g_vT  [32 * 64 * 2048];// V^T fp16 [bh][ch][seq]
__device__ __half g_atth[4096 * 1024];   // attention out fp16

// ---------------- helpers ----------------
__device__ __forceinline__ void mma_f16(float c[4],
                                        unsigned a0, unsigned a1, unsigned a2, unsigned a3,
                                        unsigned b0, unsigned b1) {
    asm volatile(
        "mma.sync.aligned.m16n8k16.row.col.f32.f16.f16.f32 "
        "{%0,%1,%2,%3}, {%4,%5,%6,%7}, {%8,%9}, {%0,%1,%2,%3};\n"
        : "+f"(c[0]), "+f"(c[1]), "+f"(c[2]), "+f"(c[3])
        : "r"(a0), "r"(a1), "r"(a2), "r"(a3), "r"(b0), "r"(b1));
}

__device__ __forceinline__ void ldsm_x4(unsigned& r0, unsigned& r1, unsigned& r2, unsigned& r3,
                                        unsigned addr) {
    asm volatile("ldmatrix.sync.aligned.m8n8.x4.shared.b16 {%0,%1,%2,%3}, [%4];\n"
                 : "=r"(r0), "=r"(r1), "=r"(r2), "=r"(r3) : "r"(addr));
}

__device__ __forceinline__ void ldsm_x2(unsigned& r0, unsigned& r1, unsigned addr) {
    asm volatile("ldmatrix.sync.aligned.m8n8.x2.shared.b16 {%0,%1}, [%2];\n"
                 : "=r"(r0), "=r"(r1) : "r"(addr));
}

__device__ __forceinline__ void cp16(void* s, const void* g) {
    unsigned sa = (unsigned)__cvta_generic_to_shared(s);
    asm volatile("cp.async.cg.shared.global [%0], [%1], 16;\n" :: "r"(sa), "l"(g));
}
__device__ __forceinline__ void cp_commit() { asm volatile("cp.async.commit_group;\n"); }
__device__ __forceinline__ void cp_wait1()  { asm volatile("cp.async.wait_group 1;\n" ::: "memory"); }

__device__ __forceinline__ unsigned pack_h2(float lo, float hi) {
    __half2 h = __floats2half2_rn(lo, hi);
    return *reinterpret_cast<unsigned*>(&h);
}

// ---------------- fp32 -> fp16 elementwise ----------------
__global__ void cvt_h_kernel(const float* __restrict__ in, __half* __restrict__ out, int n) {
    int i = (blockIdx.x * blockDim.x + threadIdx.x) * 4;
    if (i < n) {
        float4 v = *(const float4*)(in + i);
        __half2 a = __floats2half2_rn(v.x, v.y);
        __half2 b = __floats2half2_rn(v.z, v.w);
        unsigned u[2] = { *reinterpret_cast<unsigned*>(&a), *reinterpret_cast<unsigned*>(&b) };
        *(uint2*)(out + i) = *(uint2*)u;
    }
}

// ---------------- fp32 [R][C] -> fp16 [C][R] transpose ----------------
__global__ void transpose_h_kernel(const float* __restrict__ in, __half* __restrict__ out,
                                   int R, int C) {
    __shared__ __half tile[32][33];
    int c0 = blockIdx.x * 32, r0 = blockIdx.y * 32;
    int tx = threadIdx.x, ty = threadIdx.y;
#pragma unroll
    for (int s = 0; s < 4; s++)
        tile[ty + 8 * s][tx] = __float2half(in[(size_t)(r0 + ty + 8 * s) * C + c0 + tx]);
    __syncthreads();
#pragma unroll
    for (int s = 0; s < 4; s++)
        out[(size_t)(c0 + ty + 8 * s) * R + r0 + tx] = tile[tx][ty + 8 * s];
}

// ---------------- V^T extraction: qkv fp16 -> vT[bh][ch=64][seq=2048] ----------------
__global__ void vtrans_kernel(const __half* __restrict__ qkvh, __half* __restrict__ vT) {
    __shared__ __half tile[128][72];
    const int tid = threadIdx.x;
    const int chunk = blockIdx.x;
    const int bh = blockIdx.y;
    const int b = bh >> 4, h = bh & 15;
    const __half* src = qkvh + ((size_t)b * 2048 + chunk * 128) * 3072 + h * 192 + 128;
#pragma unroll
    for (int s = 0; s < 4; s++) {
        int id = tid + 256 * s;
        int r = id >> 3, c8 = (id & 7) * 8;
        *(uint4*)&tile[r][c8] = *(const uint4*)(src + (size_t)r * 3072 + c8);
    }
    __syncthreads();
    __half* dst = vT + (size_t)bh * 64 * 2048 + chunk * 128;
#pragma unroll
    for (int s = 0; s < 4; s++) {
        int id = tid + 256 * s;
        int ch = id >> 4, s8 = (id & 15) * 8;
        uint4 o;
        __half* hp = (__half*)&o;
#pragma unroll
        for (int u = 0; u < 8; u++) hp[u] = tile[s8 + u][ch];
        *(uint4*)(dst + (size_t)ch * 2048 + s8) = o;
    }
}

// ---------------- fp16 GEMM + bias: C[M,N] = A[M,K] @ BT[N,K]^T + bias ----------------
// 128x128 tile, BK=32, 128 threads (4 warps 2x2), warp tile 64x64.
// 3-stage cp.async (wait_group 1), 3 CTAs/SM.  Row pitch 80 B (20 b32: banks 20r mod 32
// = {0,20,8,28,16,4,24,12} per 8-row ldsm phase -> conflict-free).
// Stages (bytes): A s*10240 (s=0..2), B 30720 + s*10240.
#define GEMM_SMEM 61440

template<typename OutT>
__global__ __launch_bounds__(128, 3) void hgemm(
    const __half* __restrict__ A, const __half* __restrict__ BT,
    const float* __restrict__ bias, OutT* __restrict__ C,
    int M, int N, int K)
{
    extern __shared__ char smem[];
    const unsigned smem_u = (unsigned)__cvta_generic_to_shared(smem);
    const int tid = threadIdx.x;
    const int warp = tid >> 5, lane = tid & 31;
    const int g = lane >> 2, t4 = lane & 3;
    const int wm = warp >> 1, wn = warp & 1;
    const int brow = blockIdx.y * 128;
    const int bcol = blockIdx.x * 128;

    const int a_row = lane & 15;
    const int a_cb  = (lane >> 4) << 4;              // 0 / 16 bytes
    const int b_row = (lane & 7) | ((lane >> 1) & 8);
    const int b_cb  = ((lane >> 3) & 1) << 4;        // 0 / 16 bytes

    float acc[4][8][4];
#pragma unroll
    for (int i = 0; i < 4; i++)
#pragma unroll
        for (int j = 0; j < 8; j++)
#pragma unroll
            for (int r = 0; r < 4; r++) acc[i][j][r] = 0.0f;

    const __half* Ap = A + (size_t)brow * K;
    const __half* Bp = BT + (size_t)bcol * K;
    const int NT = K >> 5;

    const int f_row = tid >> 2;     // 0..31 (x4)
    const int f_c   = tid & 3;      // 16B chunk 0..3

#define G_ISSUE(t)                                                                 \
    {                                                                              \
        const int kt = (t) << 5;                                                   \
        char* As_ = smem + ((t) % 3) * 10240;                                      \
        char* Bs_ = smem + 30720 + ((t) % 3) * 10240;                              \
        _Pragma("unroll")                                                          \
        for (int s = 0; s < 4; s++) {                                              \
            int r = f_row + 32 * s;                                                \
            cp16(As_ + r * 80 + f_c * 16, Ap + (size_t)r * K + kt + f_c * 8);      \
            cp16(Bs_ + r * 80 + f_c * 16, Bp + (size_t)r * K + kt + f_c * 8);      \
        }                                                                          \
    }

    G_ISSUE(0); cp_commit();
    G_ISSUE(1); cp_commit();

    for (int t = 0; t < NT; t++) {
        cp_wait1();
        __syncthreads();

        if (t + 2 < NT) { G_ISSUE(t + 2); }
        cp_commit();   // empty group at tail keeps wait accounting uniform

        const unsigned aoff = (unsigned)((t % 3) * 10240);
        const unsigned boff = (unsigned)(30720 + (t % 3) * 10240);

#pragma unroll
        for (int ks = 0; ks < 2; ks++) {
            const int kb = ks * 32;   // bytes
            unsigned b0[8], b1[8];
#pragma unroll
            for (int jp = 0; jp < 4; jp++) {
                unsigned addr = smem_u + boff +
                    (unsigned)((wn * 64 + jp * 16 + b_row) * 80 + kb + b_cb);
                ldsm_x4(b0[2 * jp], b1[2 * jp], b0[2 * jp + 1], b1[2 * jp + 1], addr);
            }
#pragma unroll
            for (int i = 0; i < 4; i++) {
                unsigned a0, a1, a2, a3;
                unsigned addr = smem_u + aoff +
                    (unsigned)((wm * 64 + i * 16 + a_row) * 80 + kb + a_cb);
                ldsm_x4(a0, a1, a2, a3, addr);
#pragma unroll
                for (int j = 0; j < 8; j++)
                    mma_f16(acc[i][j], a0, a1, a2, a3, b0[j], b1[j]);
            }
        }
    }
#undef G_ISSUE

#pragma unroll
    for (int i = 0; i < 4; i++) {
        const size_t r0 = brow + wm * 64 + i * 16 + g;
#pragma unroll
        for (int j = 0; j < 8; j++) {
            const int c = bcol + wn * 64 + j * 8 + 2 * t4;
            float v0 = acc[i][j][0] + bias[c];
            float v1 = acc[i][j][1] + bias[c + 1];
            float v2 = acc[i][j][2] + bias[c];
            float v3 = acc[i][j][3] + bias[c + 1];
            if (sizeof(OutT) == 2) {
                *(__half2*)((__half*)C + r0 * N + c)       = __floats2half2_rn(v0, v1);
                *(__half2*)((__half*)C + (r0 + 8) * N + c) = __floats2half2_rn(v2, v3);
            } else {
                float* p0 = (float*)C + r0 * N + c;
                float* p1 = (float*)C + (r0 + 8) * N + c;
                p0[0] = v0; p0[1] = v1;
                p1[0] = v2; p1[1] = v3;
            }
        }
    }
}

// ---------------- fp16 flash attention (m32 warps, max-free, mma normalizer) ----------------
// Block: 128 q-rows x one (b,h), 128 threads (4 warps); warp w owns rows w*32..w*32+31
// (two m16 halves). K fragments reused across both halves -> half the LDSM traffic of m16.
// Q frags in registers (scaled 0.125*log2e); exp2-domain max-free softmax; normalizer l
// via ones-column mma.  K stages (bytes): 0/9216/18432; V: 27648/+; ones at 55296.
#define SEQ 2048
#define ATT_SMEM 55552
#define QSCALE 0.18033688011112042f   // 0.125 * log2(e)

__global__ __launch_bounds__(128, 2) void attn_h(
    const __half* __restrict__ qkvh, const __half* __restrict__ vT,
    __half* __restrict__ outa)
{
    extern __shared__ char smem[];
    const unsigned smem_u = (unsigned)__cvta_generic_to_shared(smem);
    const int tid = threadIdx.x;
    const int warp = tid >> 5, lane = tid & 31;
    const int g = lane >> 2, t4 = lane & 3;
    const int bh = blockIdx.y;
    const int b = bh >> 4, h = bh & 15;
    const int q0 = blockIdx.x * 128;
    const int wrow = warp * 32;

    const int b_row = (lane & 7) | ((lane >> 1) & 8);
    const int b_cb  = ((lane >> 3) & 1) << 4;   // bytes

    const __half* qb = qkvh + (size_t)b * SEQ * 3072 + h * 192;
    const __half* vb = vT + (size_t)bh * 64 * 2048;

    const int kv_r  = tid >> 3;      // 0..15 (x4)
    const int kv_c8 = tid & 7;       // 16B chunk

#define A_ISSUE(t)                                                                        \
    {                                                                                     \
        const int kt = (t) * 64;                                                          \
        char* Ks_ = smem + ((t) % 3) * 9216;                                              \
        char* Vs_ = smem + 27648 + ((t) % 3) * 9216;                                      \
        _Pragma("unroll")                                                                 \
        for (int s = 0; s < 4; s++) {                                                     \
            int r = kv_r + 16 * s;                                                        \
            cp16(Ks_ + r * 144 + kv_c8 * 16, qb + (size_t)(kt + r) * 3072 + 64 + kv_c8 * 8); \
            cp16(Vs_ + r * 144 + kv_c8 * 16, vb + (size_t)r * 2048 + kt + kv_c8 * 8);     \
        }                                                                                 \
    }

    // static ones/zeros block for the normalizer mma: row 0 = ones, rows 1-7 = zeros
    if (tid < 8) {
        __half v = (tid == 0) ? __float2half(1.0f) : __float2half(0.0f);
        __half* row = (__half*)(smem + 55296 + tid * 32);
#pragma unroll
        for (int u = 0; u < 16; u++) row[u] = v;
    }

    A_ISSUE(0); cp_commit();
    A_ISSUE(1); cp_commit();

    // Q fragments from gmem (one time), scaled by 0.125*log2e.  qa[mh][ks][4]
    unsigned qa[2][4][4];
    {
        const __half2 sc = __floats2half2_rn(QSCALE, QSCALE);
#pragma unroll
        for (int mh = 0; mh < 2; mh++) {
            const __half* qr0 = qb + (size_t)(q0 + wrow + mh * 16 + g) * 3072;
            const __half* qr1 = qr0 + (size_t)8 * 3072;
#pragma unroll
            for (int ks = 0; ks < 4; ks++) {
                __half2 v;
                v = __hmul2(*(const __half2*)(qr0 + ks * 16 + 2 * t4), sc);
                qa[mh][ks][0] = *reinterpret_cast<unsigned*>(&v);
                v = __hmul2(*(const __half2*)(qr1 + ks * 16 + 2 * t4), sc);
                qa[mh][ks][1] = *reinterpret_cast<unsigned*>(&v);
                v = __hmul2(*(const __half2*)(qr0 + ks * 16 + 2 * t4 + 8), sc);
                qa[mh][ks][2] = *reinterpret_cast<unsigned*>(&v);
                v = __hmul2(*(const __half2*)(qr1 + ks * 16 + 2 * t4 + 8), sc);
                qa[mh][ks][3] = *reinterpret_cast<unsigned*>(&v);
            }
        }
    }

    __syncthreads();  // ones block visible
    unsigned bone0, bone1;
    {
        unsigned addr = smem_u + 55296u + (unsigned)((lane & 7) * 32 + ((lane >> 3) & 1) * 16);
        ldsm_x2(bone0, bone1, addr);
    }

    float o[2][8][4], oex[2][4];
#pragma unroll
    for (int mh = 0; mh < 2; mh++) {
#pragma unroll
        for (int j = 0; j < 8; j++)
#pragma unroll
            for (int r = 0; r < 4; r++) o[mh][j][r] = 0.0f;
#pragma unroll
        for (int r = 0; r < 4; r++) oex[mh][r] = 0.0f;
    }

    for (int t = 0; t < 32; t++) {
        cp_wait1();
        __syncthreads();

        if (t + 2 < 32) { A_ISSUE(t + 2); }
        cp_commit();

        const unsigned koff = (unsigned)((t % 3) * 9216);
        const unsigned voff = (unsigned)(27648 + (t % 3) * 9216);

        // ---- S = Q @ K^T (exp2 domain) : warp m32 x n64, k=64; K frag shared by halves ----
        float sacc[2][8][4];
#pragma unroll
        for (int mh = 0; mh < 2; mh++)
#pragma unroll
            for (int j = 0; j < 8; j++)
#pragma unroll
                for (int r = 0; r < 4; r++) sacc[mh][j][r] = 0.0f;

#pragma unroll
        for (int ks = 0; ks < 4; ks++) {
            const int kb = ks * 32;   // bytes
#pragma unroll
            for (int jp = 0; jp < 4; jp++) {
                unsigned t0, t1, t2, t3;
                unsigned addr = smem_u + koff +
                    (unsigned)((jp * 16 + b_row) * 144 + kb + b_cb);
                ldsm_x4(t0, t1, t2, t3, addr);
#pragma unroll
                for (int mh = 0; mh < 2; mh++) {
                    mma_f16(sacc[mh][2 * jp],     qa[mh][ks][0], qa[mh][ks][1], qa[mh][ks][2], qa[mh][ks][3], t0, t1);
                    mma_f16(sacc[mh][2 * jp + 1], qa[mh][ks][0], qa[mh][ks][1], qa[mh][ks][2], qa[mh][ks][3], t2, t3);
                }
            }
        }

        // ---- max-free softmax: P = exp2(S) ----
        unsigned pj0[2][8], pj1[2][8];
#pragma unroll
        for (int mh = 0; mh < 2; mh++)
#pragma unroll
            for (int j = 0; j < 8; j++) {
                pj0[mh][j] = pack_h2(exp2f(sacc[mh][j][0]), exp2f(sacc[mh][j][1]));
                pj1[mh][j] = pack_h2(exp2f(sacc[mh][j][2]), exp2f(sacc[mh][j][3]));
            }

        // ---- O += P @ V, l += P @ ones : V frag shared by halves ----
#pragma unroll
        for (int ks = 0; ks < 4; ks++) {
            const int kb = ks * 32;
#pragma unroll
            for (int jp = 0; jp < 4; jp++) {
                unsigned t0, t1, t2, t3;
                unsigned addr = smem_u + voff +
                    (unsigned)((jp * 16 + b_row) * 144 + kb + b_cb);
                ldsm_x4(t0, t1, t2, t3, addr);
#pragma unroll
                for (int mh = 0; mh < 2; mh++) {
                    mma_f16(o[mh][2 * jp],     pj0[mh][2 * ks], pj1[mh][2 * ks], pj0[mh][2 * ks + 1], pj1[mh][2 * ks + 1], t0, t1);
                    mma_f16(o[mh][2 * jp + 1], pj0[mh][2 * ks], pj1[mh][2 * ks], pj0[mh][2 * ks + 1], pj1[mh][2 * ks + 1], t2, t3);
                }
            }
#pragma unroll
            for (int mh = 0; mh < 2; mh++)
                mma_f16(oex[mh], pj0[mh][2 * ks], pj1[mh][2 * ks], pj0[mh][2 * ks + 1], pj1[mh][2 * ks + 1], bone0, bone1);
        }
    }
#undef A_ISSUE

    // epilogue: normalizer lives in lanes with t4==0 -> broadcast within quad
#pragma unroll
    for (int mh = 0; mh < 2; mh++) {
        const float l0 = __shfl_sync(0xffffffffu, oex[mh][0], lane & 28);
        const float l1 = __shfl_sync(0xffffffffu, oex[mh][2], lane & 28);
        const float inv0 = 1.0f / l0, inv1 = 1.0f / l1;
        const size_t row0 = (size_t)b * SEQ + q0 + wrow + mh * 16 + g;
#pragma unroll
        for (int j = 0; j < 8; j++) {
            const int c = h * 64 + j * 8 + 2 * t4;
            *(__half2*)(outa + row0 * 1024 + c)       = __floats2half2_rn(o[mh][j][0] * inv0, o[mh][j][1] * inv0);
            *(__half2*)(outa + (row0 + 8) * 1024 + c) = __floats2half2_rn(o[mh][j][2] * inv1, o[mh][j][3] * inv1);
        }
    }
}

// ---------------- launch ----------------
extern "C" void kernel_launch(void* const* d_in, const int* in_sizes, int n_in,
                              void* d_out, int out_size)
{
    const float* x      = (const float*)d_in[0];
    const float* w_qkv  = (const float*)d_in[1];
    const float* b_qkv  = (const float*)d_in[2];
    const float* w_proj = (const float*)d_in[3];
    const float* b_proj = (const float*)d_in[4];
    float* out = (float*)d_out;

    void* p;
    cudaGetSymbolAddress(&p, g_xh);   __half* xh   = (__half*)p;
    cudaGetSymbolAddress(&p, g_wqT);  __half* wqT  = (__half*)p;
    cudaGetSymbolAddress(&p, g_wpT);  __half* wpT  = (__half*)p;
    cudaGetSymbolAddress(&p, g_qkvh); __half* qkvh = (__half*)p;
    cudaGetSymbolAddress(&p, g_vT);   __half* vT   = (__half*)p;
    cudaGetSymbolAddress(&p, g_atth); __half* atth = (__half*)p;

    cudaFuncSetAttribute(hgemm<__half>, cudaFuncAttributeMaxDynamicSharedMemorySize, GEMM_SMEM);
    cudaFuncSetAttribute(hgemm<float>,  cudaFuncAttributeMaxDynamicSharedMemorySize, GEMM_SMEM);
    cudaFuncSetAttribute(attn_h, cudaFuncAttributeMaxDynamicSharedMemorySize, ATT_SMEM);

    // precision prep: x -> fp16; weights -> fp16 transposed [N][K]
    cvt_h_kernel<<<4096, 256>>>(x, xh, 4096 * 1024);
    transpose_h_kernel<<<dim3(96, 32), dim3(32, 8)>>>(w_qkv, wqT, 1024, 3072);
    transpose_h_kernel<<<dim3(32, 32), dim3(32, 8)>>>(w_proj, wpT, 1024, 1024);

    // GEMM1: qkv = x @ w_qkv + b  (fp16 out)
    hgemm<__half><<<dim3(24, 32), 128, GEMM_SMEM>>>(xh, wqT, b_qkv, qkvh, 4096, 3072, 1024);

    // V^T extraction
    vtrans_kernel<<<dim3(16, 32), 256>>>(qkvh, vT);

    // Attention: 16 q-tiles x 32 (b,h), 2 CTAs/SM
    attn_h<<<dim3(SEQ / 128, 32), 128, ATT_SMEM>>>(qkvh, vT, atth);

    // GEMM2: out = attn @ w_proj + b (fp32 out)
    hgemm<float><<<dim3(8, 32), 128, GEMM_SMEM>>>(atth, wpT, b_proj, out, 4096, 1024, 1024);
}

// round 15
// speedup vs baseline: 1.0864x; 1.0864x over previous
#include <cuda_runtime.h>
#include <cuda_fp16.h>
#include <math.h>
#include <stdint.h>

// ---------------- scratch (fp16 pipeline) ----------------
__device__ __half g_xh  [4096 * 1024];   // x fp16
__device__ __half g_wqT [3072 * 1024];   // w_qkv^T fp16  [N][K]
__device__ __half g_wpT [1024 * 1024];   // w_proj^T fp16 [N][K]
__device__ __half g_qkvh[4096 * 3072];   // qkv fp16
__device__ __half g_vT  [32 * 64 * 2048];// V^T fp16 [bh][ch][seq]
__device__ __half g_atth[4096 * 1024];   // attention out fp16

// ---------------- helpers ----------------
__device__ __forceinline__ void mma_f16(float c[4],
                                        unsigned a0, unsigned a1, unsigned a2, unsigned a3,
                                        unsigned b0, unsigned b1) {
    asm volatile(
        "mma.sync.aligned.m16n8k16.row.col.f32.f16.f16.f32 "
        "{%0,%1,%2,%3}, {%4,%5,%6,%7}, {%8,%9}, {%0,%1,%2,%3};\n"
        : "+f"(c[0]), "+f"(c[1]), "+f"(c[2]), "+f"(c[3])
        : "r"(a0), "r"(a1), "r"(a2), "r"(a3), "r"(b0), "r"(b1));
}

__device__ __forceinline__ void ldsm_x4(unsigned& r0, unsigned& r1, unsigned& r2, unsigned& r3,
                                        unsigned addr) {
    asm volatile("ldmatrix.sync.aligned.m8n8.x4.shared.b16 {%0,%1,%2,%3}, [%4];\n"
                 : "=r"(r0), "=r"(r1), "=r"(r2), "=r"(r3) : "r"(addr));
}

__device__ __forceinline__ void ldsm_x2(unsigned& r0, unsigned& r1, unsigned addr) {
    asm volatile("ldmatrix.sync.aligned.m8n8.x2.shared.b16 {%0,%1}, [%2];\n"
                 : "=r"(r0), "=r"(r1) : "r"(addr));
}

__device__ __forceinline__ void cp16(void* s, const void* g) {
    unsigned sa = (unsigned)__cvta_generic_to_shared(s);
    asm volatile("cp.async.cg.shared.global [%0], [%1], 16;\n" :: "r"(sa), "l"(g));
}
__device__ __forceinline__ void cp_commit() { asm volatile("cp.async.commit_group;\n"); }
__device__ __forceinline__ void cp_wait1()  { asm volatile("cp.async.wait_group 1;\n" ::: "memory"); }

__device__ __forceinline__ unsigned pack_h2(float lo, float hi) {
    __half2 h = __floats2half2_rn(lo, hi);
    return *reinterpret_cast<unsigned*>(&h);
}

// ---------------- fp32 -> fp16 elementwise ----------------
__global__ void cvt_h_kernel(const float* __restrict__ in, __half* __restrict__ out, int n) {
    int i = (blockIdx.x * blockDim.x + threadIdx.x) * 4;
    if (i < n) {
        float4 v = *(const float4*)(in + i);
        __half2 a = __floats2half2_rn(v.x, v.y);
        __half2 b = __floats2half2_rn(v.z, v.w);
        unsigned u[2] = { *reinterpret_cast<unsigned*>(&a), *reinterpret_cast<unsigned*>(&b) };
        *(uint2*)(out + i) = *(uint2*)u;
    }
}

// ---------------- fp32 [R][C] -> fp16 [C][R] transpose ----------------
__global__ void transpose_h_kernel(const float* __restrict__ in, __half* __restrict__ out,
                                   int R, int C) {
    __shared__ __half tile[32][33];
    int c0 = blockIdx.x * 32, r0 = blockIdx.y * 32;
    int tx = threadIdx.x, ty = threadIdx.y;
#pragma unroll
    for (int s = 0; s < 4; s++)
        tile[ty + 8 * s][tx] = __float2half(in[(size_t)(r0 + ty + 8 * s) * C + c0 + tx]);
    __syncthreads();
#pragma unroll
    for (int s = 0; s < 4; s++)
        out[(size_t)(c0 + ty + 8 * s) * R + r0 + tx] = tile[tx][ty + 8 * s];
}

// ---------------- V^T extraction: qkv fp16 -> vT[bh][ch=64][seq=2048] ----------------
__global__ void vtrans_kernel(const __half* __restrict__ qkvh, __half* __restrict__ vT) {
    __shared__ __half tile[128][72];
    const int tid = threadIdx.x;
    const int chunk = blockIdx.x;
    const int bh = blockIdx.y;
    const int b = bh >> 4, h = bh & 15;
    const __half* src = qkvh + ((size_t)b * 2048 + chunk * 128) * 3072 + h * 192 + 128;
#pragma unroll
    for (int s = 0; s < 4; s++) {
        int id = tid + 256 * s;
        int r = id >> 3, c8 = (id & 7) * 8;
        *(uint4*)&tile[r][c8] = *(const uint4*)(src + (size_t)r * 3072 + c8);
    }
    __syncthreads();
    __half* dst = vT + (size_t)bh * 64 * 2048 + chunk * 128;
#pragma unroll
    for (int s = 0; s < 4; s++) {
        int id = tid + 256 * s;
        int ch = id >> 4, s8 = (id & 15) * 8;
        uint4 o;
        __half* hp = (__half*)&o;
#pragma unroll
        for (int u = 0; u < 8; u++) hp[u] = tile[s8 + u][ch];
        *(uint4*)(dst + (size_t)ch * 2048 + s8) = o;
    }
}

// ---------------- fp16 GEMM + bias (R12 best-measured config) ----------------
// 128x128 tile, BK=64, 256 threads (8 warps 2x4), warp 64x32, 3-stage cp.async, ldmatrix.
// Row pitch 144 B.  A stages (bytes): 0/18432/36864; B: 55296/73728/92160.
#define GEMM_SMEM 110592

template<typename OutT>
__global__ __launch_bounds__(256, 2) void hgemm(
    const __half* __restrict__ A, const __half* __restrict__ BT,
    const float* __restrict__ bias, OutT* __restrict__ C,
    int M, int N, int K)
{
    extern __shared__ char smem[];
    const unsigned smem_u = (unsigned)__cvta_generic_to_shared(smem);
    const int tid = threadIdx.x;
    const int warp = tid >> 5, lane = tid & 31;
    const int g = lane >> 2, t4 = lane & 3;
    const int wm = warp >> 2, wn = warp & 3;
    const int brow = blockIdx.y * 128;
    const int bcol = blockIdx.x * 128;

    const int a_row  = lane & 15;
    const int a_coff = (lane >> 4) << 2;             // b32
    const int b_row  = (lane & 7) | ((lane >> 1) & 8);
    const int b_coff = ((lane >> 3) & 1) << 2;       // b32

    float acc[4][4][4];
#pragma unroll
    for (int i = 0; i < 4; i++)
#pragma unroll
        for (int j = 0; j < 4; j++)
#pragma unroll
            for (int r = 0; r < 4; r++) acc[i][j][r] = 0.0f;

    const __half* Ap = A + (size_t)brow * K;
    const __half* Bp = BT + (size_t)bcol * K;
    const int NT = K >> 6;

    const int f_row = tid >> 3;     // 0..31 (x4)
    const int f_c   = tid & 7;      // 16B chunk 0..7

#define G_ISSUE(t)                                                                 \
    {                                                                              \
        const int kt = (t) << 6;                                                   \
        char* As_ = smem + ((t) % 3) * 18432;                                      \
        char* Bs_ = smem + 55296 + ((t) % 3) * 18432;                              \
        _Pragma("unroll")                                                          \
        for (int s = 0; s < 4; s++) {                                              \
            int r = f_row + 32 * s;                                                \
            cp16(As_ + r * 144 + f_c * 16, Ap + (size_t)r * K + kt + f_c * 8);     \
            cp16(Bs_ + r * 144 + f_c * 16, Bp + (size_t)r * K + kt + f_c * 8);     \
        }                                                                          \
    }

    G_ISSUE(0); cp_commit();
    G_ISSUE(1); cp_commit();

    for (int t = 0; t < NT; t++) {
        cp_wait1();
        __syncthreads();

        if (t + 2 < NT) { G_ISSUE(t + 2); }
        cp_commit();   // empty group near the tail keeps wait accounting uniform

        const unsigned aoff = (unsigned)((t % 3) * 18432);
        const unsigned boff = (unsigned)(55296 + (t % 3) * 18432);

#pragma unroll
        for (int ks = 0; ks < 4; ks++) {
            const int kb = ks * 8;   // b32
            unsigned a[4][4];
#pragma unroll
            for (int i = 0; i < 4; i++) {
                unsigned addr = smem_u + aoff +
                    (unsigned)((wm * 64 + i * 16 + a_row) * 144 + ((kb + a_coff) << 2));
                ldsm_x4(a[i][0], a[i][1], a[i][2], a[i][3], addr);
            }
            unsigned b0[4], b1[4];
#pragma unroll
            for (int jp = 0; jp < 2; jp++) {
                unsigned addr = smem_u + boff +
                    (unsigned)((wn * 32 + jp * 16 + b_row) * 144 + ((kb + b_coff) << 2));
                ldsm_x4(b0[2 * jp], b1[2 * jp], b0[2 * jp + 1], b1[2 * jp + 1], addr);
            }
#pragma unroll
            for (int i = 0; i < 4; i++)
#pragma unroll
                for (int j = 0; j < 4; j++)
                    mma_f16(acc[i][j], a[i][0], a[i][1], a[i][2], a[i][3], b0[j], b1[j]);
        }
    }
#undef G_ISSUE

#pragma unroll
    for (int i = 0; i < 4; i++) {
        const size_t r0 = brow + wm * 64 + i * 16 + g;
#pragma unroll
        for (int j = 0; j < 4; j++) {
            const int c = bcol + wn * 32 + j * 8 + 2 * t4;
            float v0 = acc[i][j][0] + bias[c];
            float v1 = acc[i][j][1] + bias[c + 1];
            float v2 = acc[i][j][2] + bias[c];
            float v3 = acc[i][j][3] + bias[c + 1];
            if (sizeof(OutT) == 2) {
                *(__half2*)((__half*)C + r0 * N + c)       = __floats2half2_rn(v0, v1);
                *(__half2*)((__half*)C + (r0 + 8) * N + c) = __floats2half2_rn(v2, v3);
            } else {
                float* p0 = (float*)C + r0 * N + c;
                float* p1 = (float*)C + (r0 + 8) * N + c;
                p0[0] = v0; p0[1] = v1;
                p1[0] = v2; p1[1] = v3;
            }
        }
    }
}

// ---------------- fp16 flash attention (R13 best-measured: max-free, mma normalizer) ----------------
// Block: 128 q-rows x one (b,h), 256 threads (8 warps); warp w owns rows w*16..w*16+15.
// Q fragments in registers (scaled by 0.125*log2e); exp2-domain max-free softmax;
// normalizer l via ones-column mma (fp32, consistent with fp16 P).
// K stages (bytes): 0/9216/18432; V: 27648/36864/46080; ones block at 55296.
#define SEQ 2048
#define ATT_SMEM 55552
#define QSCALE 0.18033688011112042f   // 0.125 * log2(e)

__global__ __launch_bounds__(256, 2) void attn_h(
    const __half* __restrict__ qkvh, const __half* __restrict__ vT,
    __half* __restrict__ outa)
{
    extern __shared__ char smem[];
    const unsigned smem_u = (unsigned)__cvta_generic_to_shared(smem);
    const int tid = threadIdx.x;
    const int warp = tid >> 5, lane = tid & 31;
    const int g = lane >> 2, t4 = lane & 3;
    const int bh = blockIdx.y;
    const int b = bh >> 4, h = bh & 15;
    const int q0 = blockIdx.x * 128;
    const int wrow = warp * 16;

    const int b_row  = (lane & 7) | ((lane >> 1) & 8);
    const int b_coff = ((lane >> 3) & 1) << 2;   // b32

    const __half* qb = qkvh + (size_t)b * SEQ * 3072 + h * 192;
    const __half* vb = vT + (size_t)bh * 64 * 2048;

    const int kv_r  = tid >> 3;      // 0..31 (x2)
    const int kv_c8 = tid & 7;       // 16B chunk

#define A_ISSUE(t)                                                                        \
    {                                                                                     \
        const int kt = (t) * 64;                                                          \
        char* Ks_ = smem + ((t) % 3) * 9216;                                              \
        char* Vs_ = smem + 27648 + ((t) % 3) * 9216;                                      \
        _Pragma("unroll")                                                                 \
        for (int s = 0; s < 2; s++) {                                                     \
            int r = kv_r + 32 * s;                                                        \
            cp16(Ks_ + r * 144 + kv_c8 * 16, qb + (size_t)(kt + r) * 3072 + 64 + kv_c8 * 8); \
            cp16(Vs_ + r * 144 + kv_c8 * 16, vb + (size_t)r * 2048 + kt + kv_c8 * 8);     \
        }                                                                                 \
    }

    // static ones/zeros block for the normalizer mma: row 0 = ones, rows 1-7 = zeros
    if (tid < 8) {
        __half v = (tid == 0) ? __float2half(1.0f) : __float2half(0.0f);
        __half* row = (__half*)(smem + 55296 + tid * 32);
#pragma unroll
        for (int u = 0; u < 16; u++) row[u] = v;
    }

    A_ISSUE(0); cp_commit();
    A_ISSUE(1); cp_commit();

    // Q fragments straight from gmem (one time), scaled by 0.125*log2e
    unsigned qa0[4], qa1[4], qa2[4], qa3[4];
    {
        const __half2 sc = __floats2half2_rn(QSCALE, QSCALE);
        const __half* qr0 = qb + (size_t)(q0 + wrow + g) * 3072;
        const __half* qr1 = qr0 + (size_t)8 * 3072;
#pragma unroll
        for (int ks = 0; ks < 4; ks++) {
            __half2 v;
            v = __hmul2(*(const __half2*)(qr0 + ks * 16 + 2 * t4), sc);
            qa0[ks] = *reinterpret_cast<unsigned*>(&v);
            v = __hmul2(*(const __half2*)(qr1 + ks * 16 + 2 * t4), sc);
            qa1[ks] = *reinterpret_cast<unsigned*>(&v);
            v = __hmul2(*(const __half2*)(qr0 + ks * 16 + 2 * t4 + 8), sc);
            qa2[ks] = *reinterpret_cast<unsigned*>(&v);
            v = __hmul2(*(const __half2*)(qr1 + ks * 16 + 2 * t4 + 8), sc);
            qa3[ks] = *reinterpret_cast<unsigned*>(&v);
        }
    }

    __syncthreads();  // ones block visible
    unsigned bone0, bone1;
    {
        unsigned addr = smem_u + 55296u + (unsigned)((lane & 7) * 32 + ((lane >> 3) & 1) * 16);
        ldsm_x2(bone0, bone1, addr);
    }

    float o[8][4], oex[4];
#pragma unroll
    for (int j = 0; j < 8; j++)
#pragma unroll
        for (int r = 0; r < 4; r++) o[j][r] = 0.0f;
#pragma unroll
    for (int r = 0; r < 4; r++) oex[r] = 0.0f;

    for (int t = 0; t < 32; t++) {
        cp_wait1();
        __syncthreads();

        if (t + 2 < 32) { A_ISSUE(t + 2); }
        cp_commit();

        const unsigned koff = (unsigned)((t % 3) * 9216);
        const unsigned voff = (unsigned)(27648 + (t % 3) * 9216);

        // ---- S = Q @ K^T (exp2 domain) : warp m16 x n64, k=64 ----
        float sacc[8][4];
#pragma unroll
        for (int j = 0; j < 8; j++)
#pragma unroll
            for (int r = 0; r < 4; r++) sacc[j][r] = 0.0f;

#pragma unroll
        for (int ks = 0; ks < 4; ks++) {
            const int kb = ks * 8;
#pragma unroll
            for (int jp = 0; jp < 4; jp++) {
                unsigned t0, t1, t2, t3;
                unsigned addr = smem_u + koff +
                    (unsigned)((jp * 16 + b_row) * 144 + ((kb + b_coff) << 2));
                ldsm_x4(t0, t1, t2, t3, addr);
                mma_f16(sacc[2 * jp],     qa0[ks], qa1[ks], qa2[ks], qa3[ks], t0, t1);
                mma_f16(sacc[2 * jp + 1], qa0[ks], qa1[ks], qa2[ks], qa3[ks], t2, t3);
            }
        }

        // ---- max-free softmax: P = exp2(S) ----
        unsigned pj0[8], pj1[8];
#pragma unroll
        for (int j = 0; j < 8; j++) {
            pj0[j] = pack_h2(exp2f(sacc[j][0]), exp2f(sacc[j][1]));
            pj1[j] = pack_h2(exp2f(sacc[j][2]), exp2f(sacc[j][3]));
        }

        // ---- O += P @ V, plus l += P @ ones : warp m16 x n64(+8), k=64 ----
#pragma unroll
        for (int ks = 0; ks < 4; ks++) {
            const int kb = ks * 8;
#pragma unroll
            for (int jp = 0; jp < 4; jp++) {
                unsigned t0, t1, t2, t3;
                unsigned addr = smem_u + voff +
                    (unsigned)((jp * 16 + b_row) * 144 + ((kb + b_coff) << 2));
                ldsm_x4(t0, t1, t2, t3, addr);
                mma_f16(o[2 * jp],     pj0[2 * ks], pj1[2 * ks], pj0[2 * ks + 1], pj1[2 * ks + 1], t0, t1);
                mma_f16(o[2 * jp + 1], pj0[2 * ks], pj1[2 * ks], pj0[2 * ks + 1], pj1[2 * ks + 1], t2, t3);
            }
            mma_f16(oex, pj0[2 * ks], pj1[2 * ks], pj0[2 * ks + 1], pj1[2 * ks + 1], bone0, bone1);
        }
    }
#undef A_ISSUE

    // normalizer lives in lanes with t4==0 (col 0 of the ones n8 group) -> broadcast
    const float l0 = __shfl_sync(0xffffffffu, oex[0], lane & 28);
    const float l1 = __shfl_sync(0xffffffffu, oex[2], lane & 28);
    const float inv0 = 1.0f / l0, inv1 = 1.0f / l1;
    const size_t row0 = (size_t)b * SEQ + q0 + wrow + g;
#pragma unroll
    for (int j = 0; j < 8; j++) {
        const int c = h * 64 + j * 8 + 2 * t4;
        *(__half2*)(outa + row0 * 1024 + c)       = __floats2half2_rn(o[j][0] * inv0, o[j][1] * inv0);
        *(__half2*)(outa + (row0 + 8) * 1024 + c) = __floats2half2_rn(o[j][2] * inv1, o[j][3] * inv1);
    }
}

// ---------------- launch ----------------
extern "C" void kernel_launch(void* const* d_in, const int* in_sizes, int n_in,
                              void* d_out, int out_size)
{
    const float* x      = (const float*)d_in[0];
    const float* w_qkv  = (const float*)d_in[1];
    const float* b_qkv  = (const float*)d_in[2];
    const float* w_proj = (const float*)d_in[3];
    const float* b_proj = (const float*)d_in[4];
    float* out = (float*)d_out;

    void* p;
    cudaGetSymbolAddress(&p, g_xh);   __half* xh   = (__half*)p;
    cudaGetSymbolAddress(&p, g_wqT);  __half* wqT  = (__half*)p;
    cudaGetSymbolAddress(&p, g_wpT);  __half* wpT  = (__half*)p;
    cudaGetSymbolAddress(&p, g_qkvh); __half* qkvh = (__half*)p;
    cudaGetSymbolAddress(&p, g_vT);   __half* vT   = (__half*)p;
    cudaGetSymbolAddress(&p, g_atth); __half* atth = (__half*)p;

    cudaFuncSetAttribute(hgemm<__half>, cudaFuncAttributeMaxDynamicSharedMemorySize, GEMM_SMEM);
    cudaFuncSetAttribute(hgemm<float>,  cudaFuncAttributeMaxDynamicSharedMemorySize, GEMM_SMEM);
    cudaFuncSetAttribute(attn_h, cudaFuncAttributeMaxDynamicSharedMemorySize, ATT_SMEM);

    // precision prep: x -> fp16; weights -> fp16 transposed [N][K]
    cvt_h_kernel<<<4096, 256>>>(x, xh, 4096 * 1024);
    transpose_h_kernel<<<dim3(96, 32), dim3(32, 8)>>>(w_qkv, wqT, 1024, 3072);
    transpose_h_kernel<<<dim3(32, 32), dim3(32, 8)>>>(w_proj, wpT, 1024, 1024);

    // GEMM1: qkv = x @ w_qkv + b  (fp16 out)
    hgemm<__half><<<dim3(24, 32), 256, GEMM_SMEM>>>(xh, wqT, b_qkv, qkvh, 4096, 3072, 1024);

    // V^T extraction
    vtrans_kernel<<<dim3(16, 32), 256>>>(qkvh, vT);

    // Attention: 16 q-tiles x 32 (b,h), 2 CTAs/SM
    attn_h<<<dim3(SEQ / 128, 32), 256, ATT_SMEM>>>(qkvh, vT, atth);

    // GEMM2: out = attn @ w_proj + b (fp32 out)
    hgemm<float><<<dim3(8, 32), 256, GEMM_SMEM>>>(atth, wpT, b_proj, out, 4096, 1024, 1024);
}

// round 17
// speedup vs baseline: 1.1292x; 1.0394x over previous
#include <cuda_runtime.h>
#include <cuda_fp16.h>
#include <math.h>
#include <stdint.h>

// ---------------- scratch (fp16 pipeline) ----------------
__device__ __half g_xh  [4096 * 1024];   // x fp16
__device__ __half g_wqT [3072 * 1024];   // w_qkv^T fp16  [N][K]
__device__ __half g_wpT [1024 * 1024];   // w_proj^T fp16 [N][K]
__device__ __half g_qkvh[4096 * 3072];   // qkv fp16
__device__ __half g_atth[4096 * 1024];   // attention out fp16

// ---------------- helpers ----------------
__device__ __forceinline__ void mma_f16(float c[4],
                                        unsigned a0, unsigned a1, unsigned a2, unsigned a3,
                                        unsigned b0, unsigned b1) {
    asm volatile(
        "mma.sync.aligned.m16n8k16.row.col.f32.f16.f16.f32 "
        "{%0,%1,%2,%3}, {%4,%5,%6,%7}, {%8,%9}, {%0,%1,%2,%3};\n"
        : "+f"(c[0]), "+f"(c[1]), "+f"(c[2]), "+f"(c[3])
        : "r"(a0), "r"(a1), "r"(a2), "r"(a3), "r"(b0), "r"(b1));
}

__device__ __forceinline__ void ldsm_x4(unsigned& r0, unsigned& r1, unsigned& r2, unsigned& r3,
                                        unsigned addr) {
    asm volatile("ldmatrix.sync.aligned.m8n8.x4.shared.b16 {%0,%1,%2,%3}, [%4];\n"
                 : "=r"(r0), "=r"(r1), "=r"(r2), "=r"(r3) : "r"(addr));
}

__device__ __forceinline__ void ldsm_x4_t(unsigned& r0, unsigned& r1, unsigned& r2, unsigned& r3,
                                          unsigned addr) {
    asm volatile("ldmatrix.sync.aligned.m8n8.x4.trans.shared.b16 {%0,%1,%2,%3}, [%4];\n"
                 : "=r"(r0), "=r"(r1), "=r"(r2), "=r"(r3) : "r"(addr));
}

__device__ __forceinline__ void ldsm_x2(unsigned& r0, unsigned& r1, unsigned addr) {
    asm volatile("ldmatrix.sync.aligned.m8n8.x2.shared.b16 {%0,%1}, [%2];\n"
                 : "=r"(r0), "=r"(r1) : "r"(addr));
}

__device__ __forceinline__ void cp16(void* s, const void* g) {
    unsigned sa = (unsigned)__cvta_generic_to_shared(s);
    asm volatile("cp.async.cg.shared.global [%0], [%1], 16;\n" :: "r"(sa), "l"(g));
}
__device__ __forceinline__ void cp_commit() { asm volatile("cp.async.commit_group;\n"); }
__device__ __forceinline__ void cp_wait1()  { asm volatile("cp.async.wait_group 1;\n" ::: "memory"); }

__device__ __forceinline__ unsigned pack_h2(float lo, float hi) {
    __half2 h = __floats2half2_rn(lo, hi);
    return *reinterpret_cast<unsigned*>(&h);
}

// ---------------- fp32 -> fp16 elementwise ----------------
__global__ void cvt_h_kernel(const float* __restrict__ in, __half* __restrict__ out, int n) {
    int i = (blockIdx.x * blockDim.x + threadIdx.x) * 4;
    if (i < n) {
        float4 v = *(const float4*)(in + i);
        __half2 a = __floats2half2_rn(v.x, v.y);
        __half2 b = __floats2half2_rn(v.z, v.w);
        unsigned u[2] = { *reinterpret_cast<unsigned*>(&a), *reinterpret_cast<unsigned*>(&b) };
        *(uint2*)(out + i) = *(uint2*)u;
    }
}

// ---------------- fp32 [R][C] -> fp16 [C][R] transpose ----------------
__global__ void transpose_h_kernel(const float* __restrict__ in, __half* __restrict__ out,
                                   int R, int C) {
    __shared__ __half tile[32][33];
    int c0 = blockIdx.x * 32, r0 = blockIdx.y * 32;
    int tx = threadIdx.x, ty = threadIdx.y;
#pragma unroll
    for (int s = 0; s < 4; s++)
        tile[ty + 8 * s][tx] = __float2half(in[(size_t)(r0 + ty + 8 * s) * C + c0 + tx]);
    __syncthreads();
#pragma unroll
    for (int s = 0; s < 4; s++)
        out[(size_t)(c0 + ty + 8 * s) * R + r0 + tx] = tile[tx][ty + 8 * s];
}

// ---------------- fp16 GEMM + bias (R12/R15 best-measured config) ----------------
// 128x128 tile, BK=64, 256 threads (8 warps 2x4), warp 64x32, 3-stage cp.async, ldmatrix.
// Row pitch 144 B.  A stages (bytes): 0/18432/36864; B: 55296/73728/92160.
#define GEMM_SMEM 110592

template<typename OutT>
__global__ __launch_bounds__(256, 2) void hgemm(
    const __half* __restrict__ A, const __half* __restrict__ BT,
    const float* __restrict__ bias, OutT* __restrict__ C,
    int M, int N, int K)
{
    extern __shared__ char smem[];
    const unsigned smem_u = (unsigned)__cvta_generic_to_shared(smem);
    const int tid = threadIdx.x;
    const int warp = tid >> 5, lane = tid & 31;
    const int g = lane >> 2, t4 = lane & 3;
    const int wm = warp >> 2, wn = warp & 3;
    const int brow = blockIdx.y * 128;
    const int bcol = blockIdx.x * 128;

    const int a_row  = lane & 15;
    const int a_coff = (lane >> 4) << 2;             // b32
    const int b_row  = (lane & 7) | ((lane >> 1) & 8);
    const int b_coff = ((lane >> 3) & 1) << 2;       // b32

    float acc[4][4][4];
#pragma unroll
    for (int i = 0; i < 4; i++)
#pragma unroll
        for (int j = 0; j < 4; j++)
#pragma unroll
            for (int r = 0; r < 4; r++) acc[i][j][r] = 0.0f;

    const __half* Ap = A + (size_t)brow * K;
    const __half* Bp = BT + (size_t)bcol * K;
    const int NT = K >> 6;

    const int f_row = tid >> 3;     // 0..31 (x4)
    const int f_c   = tid & 7;      // 16B chunk 0..7

#define G_ISSUE(t)                                                                 \
    {                                                                              \
        const int kt = (t) << 6;                                                   \
        char* As_ = smem + ((t) % 3) * 18432;                                      \
        char* Bs_ = smem + 55296 + ((t) % 3) * 18432;                              \
        _Pragma("unroll")                                                          \
        for (int s = 0; s < 4; s++) {                                              \
            int r = f_row + 32 * s;                                                \
            cp16(As_ + r * 144 + f_c * 16, Ap + (size_t)r * K + kt + f_c * 8);     \
            cp16(Bs_ + r * 144 + f_c * 16, Bp + (size_t)r * K + kt + f_c * 8);     \
        }                                                                          \
    }

    G_ISSUE(0); cp_commit();
    G_ISSUE(1); cp_commit();

    for (int t = 0; t < NT; t++) {
        cp_wait1();
        __syncthreads();

        if (t + 2 < NT) { G_ISSUE(t + 2); }
        cp_commit();   // empty group near the tail keeps wait accounting uniform

        const unsigned aoff = (unsigned)((t % 3) * 18432);
        const unsigned boff = (unsigned)(55296 + (t % 3) * 18432);

#pragma unroll
        for (int ks = 0; ks < 4; ks++) {
            const int kb = ks * 8;   // b32
            unsigned a[4][4];
#pragma unroll
            for (int i = 0; i < 4; i++) {
                unsigned addr = smem_u + aoff +
                    (unsigned)((wm * 64 + i * 16 + a_row) * 144 + ((kb + a_coff) << 2));
                ldsm_x4(a[i][0], a[i][1], a[i][2], a[i][3], addr);
            }
            unsigned b0[4], b1[4];
#pragma unroll
            for (int jp = 0; jp < 2; jp++) {
                unsigned addr = smem_u + boff +
                    (unsigned)((wn * 32 + jp * 16 + b_row) * 144 + ((kb + b_coff) << 2));
                ldsm_x4(b0[2 * jp], b1[2 * jp], b0[2 * jp + 1], b1[2 * jp + 1], addr);
            }
#pragma unroll
            for (int i = 0; i < 4; i++)
#pragma unroll
                for (int j = 0; j < 4; j++)
                    mma_f16(acc[i][j], a[i][0], a[i][1], a[i][2], a[i][3], b0[j], b1[j]);
        }
    }
#undef G_ISSUE

#pragma unroll
    for (int i = 0; i < 4; i++) {
        const size_t r0 = brow + wm * 64 + i * 16 + g;
#pragma unroll
        for (int j = 0; j < 4; j++) {
            const int c = bcol + wn * 32 + j * 8 + 2 * t4;
            float v0 = acc[i][j][0] + bias[c];
            float v1 = acc[i][j][1] + bias[c + 1];
            float v2 = acc[i][j][2] + bias[c];
            float v3 = acc[i][j][3] + bias[c + 1];
            if (sizeof(OutT) == 2) {
                *(__half2*)((__half*)C + r0 * N + c)       = __floats2half2_rn(v0, v1);
                *(__half2*)((__half*)C + (r0 + 8) * N + c) = __floats2half2_rn(v2, v3);
            } else {
                float* p0 = (float*)C + r0 * N + c;
                float* p1 = (float*)C + (r0 + 8) * N + c;
                p0[0] = v0; p0[1] = v1;
                p1[0] = v2; p1[1] = v3;
            }
        }
    }
}

// ---------------- fp16 flash attention (combined KV tile + ldsm.trans V) ----------------
// Block: 128 q-rows x one (b,h), 256 threads (8 warps); warp w owns rows w*16..w*16+15.
// K and V are adjacent in the qkv row (+64..+192 halves = 256 B): one combined KV tile
// [64 keys][256 B] per key-tile, pitch 272 B (68 b32 = 4 mod 32 -> conflict-free).
// K frags: non-trans ldsm on bytes [0,128); V frags: ldsm.x4.trans on bytes [128,256).
// Q frags in registers (scaled 0.125*log2e); exp2-domain max-free softmax; normalizer l
// via ones-column mma.  KV stages (bytes): s*17408 (s=0..2); ones block at 52224.
#define SEQ 2048
#define ATT_SMEM 52480
#define QSCALE 0.18033688011112042f   // 0.125 * log2(e)

__global__ __launch_bounds__(256, 2) void attn_h(
    const __half* __restrict__ qkvh, __half* __restrict__ outa)
{
    extern __shared__ char smem[];
    const unsigned smem_u = (unsigned)__cvta_generic_to_shared(smem);
    const int tid = threadIdx.x;
    const int warp = tid >> 5, lane = tid & 31;
    const int g = lane >> 2, t4 = lane & 3;
    const int bh = blockIdx.y;
    const int b = bh >> 4, h = bh & 15;
    const int q0 = blockIdx.x * 128;
    const int wrow = warp * 16;

    // K fragment geometry (non-trans ldsm; n=keys rows, k=ch chunks)
    const int b_row = (lane & 7) | ((lane >> 1) & 8);
    const int b_cb  = ((lane >> 3) & 1) << 4;        // bytes

    // V fragment geometry (trans ldsm; stored [key][ch])
    const int vq      = lane >> 3;                   // quad 0..3
    const int v_rowoff = ((vq & 1) << 3) | (lane & 7);  // key row 0..15 within k16 block
    const int v_cboff  = (vq >> 1) << 4;             // ch byte offset 0/16

    const __half* qb = qkvh + (size_t)b * SEQ * 3072 + h * 192;

    const int kv_r   = tid >> 4;     // 0..15 (x4)
    const int kv_c16 = tid & 15;     // 16B chunk 0..15 (covers K|V 256 B)

#define A_ISSUE(t)                                                                        \
    {                                                                                     \
        const int kt = (t) * 64;                                                          \
        char* KV_ = smem + ((t) % 3) * 17408;                                             \
        _Pragma("unroll")                                                                 \
        for (int s = 0; s < 4; s++) {                                                     \
            int r = kv_r + 16 * s;                                                        \
            cp16(KV_ + r * 272 + kv_c16 * 16, qb + (size_t)(kt + r) * 3072 + 64 + kv_c16 * 8); \
        }                                                                                 \
    }

    // static ones/zeros block for the normalizer mma: row 0 = ones, rows 1-7 = zeros
    if (tid < 8) {
        __half v = (tid == 0) ? __float2half(1.0f) : __float2half(0.0f);
        __half* row = (__half*)(smem + 52224 + tid * 32);
#pragma unroll
        for (int u = 0; u < 16; u++) row[u] = v;
    }

    A_ISSUE(0); cp_commit();
    A_ISSUE(1); cp_commit();

    // Q fragments straight from gmem (one time), scaled by 0.125*log2e
    unsigned qa0[4], qa1[4], qa2[4], qa3[4];
    {
        const __half2 sc = __floats2half2_rn(QSCALE, QSCALE);
        const __half* qr0 = qb + (size_t)(q0 + wrow + g) * 3072;
        const __half* qr1 = qr0 + (size_t)8 * 3072;
#pragma unroll
        for (int ks = 0; ks < 4; ks++) {
            __half2 v;
            v = __hmul2(*(const __half2*)(qr0 + ks * 16 + 2 * t4), sc);
            qa0[ks] = *reinterpret_cast<unsigned*>(&v);
            v = __hmul2(*(const __half2*)(qr1 + ks * 16 + 2 * t4), sc);
            qa1[ks] = *reinterpret_cast<unsigned*>(&v);
            v = __hmul2(*(const __half2*)(qr0 + ks * 16 + 2 * t4 + 8), sc);
            qa2[ks] = *reinterpret_cast<unsigned*>(&v);
            v = __hmul2(*(const __half2*)(qr1 + ks * 16 + 2 * t4 + 8), sc);
            qa3[ks] = *reinterpret_cast<unsigned*>(&v);
        }
    }

    __syncthreads();  // ones block visible
    unsigned bone0, bone1;
    {
        unsigned addr = smem_u + 52224u + (unsigned)((lane & 7) * 32 + ((lane >> 3) & 1) * 16);
        ldsm_x2(bone0, bone1, addr);
    }

    float o[8][4], oex[4];
#pragma unroll
    for (int j = 0; j < 8; j++)
#pragma unroll
        for (int r = 0; r < 4; r++) o[j][r] = 0.0f;
#pragma unroll
    for (int r = 0; r < 4; r++) oex[r] = 0.0f;

    for (int t = 0; t < 32; t++) {
        cp_wait1();
        __syncthreads();

        if (t + 2 < 32) { A_ISSUE(t + 2); }
        cp_commit();

        const unsigned kvoff = (unsigned)((t % 3) * 17408);

        // ---- S = Q @ K^T (exp2 domain) : warp m16 x n64, k=64 ----
        float sacc[8][4];
#pragma unroll
        for (int j = 0; j < 8; j++)
#pragma unroll
            for (int r = 0; r < 4; r++) sacc[j][r] = 0.0f;

#pragma unroll
        for (int ks = 0; ks < 4; ks++) {
            const int kb = ks * 32;   // ch bytes
#pragma unroll
            for (int jp = 0; jp < 4; jp++) {
                unsigned t0, t1, t2, t3;
                unsigned addr = smem_u + kvoff +
                    (unsigned)((jp * 16 + b_row) * 272 + kb + b_cb);
                ldsm_x4(t0, t1, t2, t3, addr);
                mma_f16(sacc[2 * jp],     qa0[ks], qa1[ks], qa2[ks], qa3[ks], t0, t1);
                mma_f16(sacc[2 * jp + 1], qa0[ks], qa1[ks], qa2[ks], qa3[ks], t2, t3);
            }
        }

        // ---- max-free softmax: P = exp2(S) ----
        unsigned pj0[8], pj1[8];
#pragma unroll
        for (int j = 0; j < 8; j++) {
            pj0[j] = pack_h2(exp2f(sacc[j][0]), exp2f(sacc[j][1]));
            pj1[j] = pack_h2(exp2f(sacc[j][2]), exp2f(sacc[j][3]));
        }

        // ---- O += P @ V, plus l += P @ ones : V frags via ldsm.trans on [key][ch] ----
#pragma unroll
        for (int ks = 0; ks < 4; ks++) {
#pragma unroll
            for (int jp = 0; jp < 4; jp++) {
                unsigned t0, t1, t2, t3;
                unsigned addr = smem_u + kvoff +
                    (unsigned)((ks * 16 + v_rowoff) * 272 + 128 + jp * 32 + v_cboff);
                ldsm_x4_t(t0, t1, t2, t3, addr);
                mma_f16(o[2 * jp],     pj0[2 * ks], pj1[2 * ks], pj0[2 * ks + 1], pj1[2 * ks + 1], t0, t1);
                mma_f16(o[2 * jp + 1], pj0[2 * ks], pj1[2 * ks], pj0[2 * ks + 1], pj1[2 * ks + 1], t2, t3);
            }
            mma_f16(oex, pj0[2 * ks], pj1[2 * ks], pj0[2 * ks + 1], pj1[2 * ks + 1], bone0, bone1);
        }
    }
#undef A_ISSUE

    // normalizer lives in lanes with t4==0 (col 0 of the ones n8 group) -> broadcast
    const float l0 = __shfl_sync(0xffffffffu, oex[0], lane & 28);
    const float l1 = __shfl_sync(0xffffffffu, oex[2], lane & 28);
    const float inv0 = 1.0f / l0, inv1 = 1.0f / l1;
    const size_t row0 = (size_t)b * SEQ + q0 + wrow + g;
#pragma unroll
    for (int j = 0; j < 8; j++) {
        const int c = h * 64 + j * 8 + 2 * t4;
        *(__half2*)(outa + row0 * 1024 + c)       = __floats2half2_rn(o[j][0] * inv0, o[j][1] * inv0);
        *(__half2*)(outa + (row0 + 8) * 1024 + c) = __floats2half2_rn(o[j][2] * inv1, o[j][3] * inv1);
    }
}

// ---------------- launch ----------------
extern "C" void kernel_launch(void* const* d_in, const int* in_sizes, int n_in,
                              void* d_out, int out_size)
{
    const float* x      = (const float*)d_in[0];
    const float* w_qkv  = (const float*)d_in[1];
    const float* b_qkv  = (const float*)d_in[2];
    const float* w_proj = (const float*)d_in[3];
    const float* b_proj = (const float*)d_in[4];
    float* out = (float*)d_out;

    void* p;
    cudaGetSymbolAddress(&p, g_xh);   __half* xh   = (__half*)p;
    cudaGetSymbolAddress(&p, g_wqT);  __half* wqT  = (__half*)p;
    cudaGetSymbolAddress(&p, g_wpT);  __half* wpT  = (__half*)p;
    cudaGetSymbolAddress(&p, g_qkvh); __half* qkvh = (__half*)p;
    cudaGetSymbolAddress(&p, g_atth); __half* atth = (__half*)p;

    cudaFuncSetAttribute(hgemm<__half>, cudaFuncAttributeMaxDynamicSharedMemorySize, GEMM_SMEM);
    cudaFuncSetAttribute(hgemm<float>,  cudaFuncAttributeMaxDynamicSharedMemorySize, GEMM_SMEM);
    cudaFuncSetAttribute(attn_h, cudaFuncAttributeMaxDynamicSharedMemorySize, ATT_SMEM);

    // precision prep: x -> fp16; weights -> fp16 transposed [N][K]
    cvt_h_kernel<<<4096, 256>>>(x, xh, 4096 * 1024);
    transpose_h_kernel<<<dim3(96, 32), dim3(32, 8)>>>(w_qkv, wqT, 1024, 3072);
    transpose_h_kernel<<<dim3(32, 32), dim3(32, 8)>>>(w_proj, wpT, 1024, 1024);

    // GEMM1: qkv = x @ w_qkv + b  (fp16 out)
    hgemm<__half><<<dim3(24, 32), 256, GEMM_SMEM>>>(xh, wqT, b_qkv, qkvh, 4096, 3072, 1024);

    // Attention: 16 q-tiles x 32 (b,h), 2 CTAs/SM  (V read in-place via ldsm.trans)
    attn_h<<<dim3(SEQ / 128, 32), 256, ATT_SMEM>>>(qkvh, atth);

    // GEMM2: out = attn @ w_proj + b (fp32 out)
    hgemm<float><<<dim3(8, 32), 256, GEMM_SMEM>>>(atth, wpT, b_proj, out, 4096, 1024, 1024);
}